// round 3
// baseline (speedup 1.0000x reference)
#include <cuda_runtime.h>
#include <math.h>

#define N_NODES 50000
#define N_EDGES 800000
#define DIM 128
#define NUM_HEADS 8
#define HEAD_DIM 16

#define BM 64
#define BK 16
#define BN 128

// Scratch (static device globals -- allocation-free per harness rules)
__device__ float gQ[N_NODES * DIM];
__device__ float gK[N_NODES * DIM];
__device__ float gV[N_NODES * DIM];
__device__ float gZ[N_NODES * NUM_HEADS];

__device__ __forceinline__ void red_add_v4(float* addr, float4 v) {
    asm volatile("red.global.add.v4.f32 [%0], {%1,%2,%3,%4};"
                 :: "l"(addr), "f"(v.x), "f"(v.y), "f"(v.z), "f"(v.w)
                 : "memory");
}

// ---------------------------------------------------------------------------
// Zero init: d_out (wV accumulator) and gZ
// ---------------------------------------------------------------------------
__global__ void zero_kernel(float* __restrict__ out) {
    int i = blockIdx.x * blockDim.x + threadIdx.x;
    if (i < N_NODES * DIM) out[i] = 0.f;
    if (i < N_NODES * NUM_HEADS) gZ[i] = 0.f;
}

// ---------------------------------------------------------------------------
// 64x128 fp32 GEMM tile: out_tile = A[row0:row0+64, 0:128] @ W[128,128] + bias
// 256 threads, 4x8 micro-tile per thread, BK=16.
// ---------------------------------------------------------------------------
__device__ __forceinline__ void gemm64x128(
    const float* __restrict__ A,
    const float* __restrict__ W,
    const float* __restrict__ bias,
    int row0, int M, bool guard,
    float (&acc)[4][8],
    float (*As)[BM + 1],    // [BK][BM+1]
    float (*Bs)[BN])        // [BK][BN]
{
    const int tid = threadIdx.x;
    const int tx = tid & 15;   // col group (8 cols each)
    const int ty = tid >> 4;   // row group (4 rows each)

#pragma unroll
    for (int i = 0; i < 4; i++)
#pragma unroll
        for (int j = 0; j < 8; j++) acc[i][j] = 0.f;

    for (int k0 = 0; k0 < DIM; k0 += BK) {
        // A tile: 64 rows x 16 k; each thread loads one float4 along k
        {
            int idx = tid * 4;          // 0..1023
            int m = idx >> 4;
            int k = idx & 15;
            float4 a;
            int grow = row0 + m;
            if (!guard || grow < M)
                a = *(const float4*)(A + (size_t)grow * DIM + k0 + k);
            else
                a = make_float4(0.f, 0.f, 0.f, 0.f);
            As[k + 0][m] = a.x;
            As[k + 1][m] = a.y;
            As[k + 2][m] = a.z;
            As[k + 3][m] = a.w;
        }
        // B tile: 16 x 128; each thread loads 2 float4
        {
#pragma unroll
            for (int r = 0; r < 2; r++) {
                int idx = tid * 8 + r * 4;   // 0..2047
                int k = idx >> 7;
                int n = idx & 127;
                *(float4*)&Bs[k][n] = *(const float4*)(W + (size_t)(k0 + k) * DIM + n);
            }
        }
        __syncthreads();

#pragma unroll
        for (int k = 0; k < BK; k++) {
            float a[4], b[8];
#pragma unroll
            for (int i = 0; i < 4; i++) a[i] = As[k][ty * 4 + i];
#pragma unroll
            for (int j = 0; j < 8; j++) b[j] = Bs[k][tx * 8 + j];
#pragma unroll
            for (int i = 0; i < 4; i++)
#pragma unroll
                for (int j = 0; j < 8; j++) acc[i][j] += a[i] * b[j];
        }
        __syncthreads();
    }

#pragma unroll
    for (int j = 0; j < 8; j++) {
        float bv = bias[tx * 8 + j];
#pragma unroll
        for (int i = 0; i < 4; i++) acc[i][j] += bv;
    }
}

// ---------------------------------------------------------------------------
// QKV projections: grid.z in {0,1,2} -> (Wq,bq,gQ), (Wk,bk,gK), (Wv,bv,gV)
// ---------------------------------------------------------------------------
__global__ __launch_bounds__(256) void qkv_kernel(
    const float* __restrict__ x,
    const float* __restrict__ Wq, const float* __restrict__ bq,
    const float* __restrict__ Wk, const float* __restrict__ bk,
    const float* __restrict__ Wv, const float* __restrict__ bv)
{
    __shared__ float As[BK][BM + 1];
    __shared__ float Bs[BK][BN];

    const float* W;
    const float* b;
    float* out;
    if (blockIdx.z == 0)      { W = Wq; b = bq; out = gQ; }
    else if (blockIdx.z == 1) { W = Wk; b = bk; out = gK; }
    else                      { W = Wv; b = bv; out = gV; }

    int row0 = blockIdx.x * BM;
    float acc[4][8];
    gemm64x128(x, W, b, row0, N_NODES, true, acc, As, Bs);

    const int tid = threadIdx.x;
    const int tx = tid & 15;
    const int ty = tid >> 4;

#pragma unroll
    for (int i = 0; i < 4; i++) {
        int r = row0 + ty * 4 + i;
        if (r < N_NODES) {
            float* o = out + (size_t)r * DIM + tx * 8;
            *(float4*)(o + 0) = make_float4(acc[i][0], acc[i][1], acc[i][2], acc[i][3]);
            *(float4*)(o + 4) = make_float4(acc[i][4], acc[i][5], acc[i][6], acc[i][7]);
        }
    }
}

// ---------------------------------------------------------------------------
// Fused edge kernel: E = edge_attr @ We + be (64-edge tile, kept in SMEM),
// per-(edge,head) score = exp(clip(sum_d K[src]*Q[dst]*E/4, -5, 5)),
// vectorized red.global atomics for wV (d_out) and Z.
// ---------------------------------------------------------------------------
__global__ __launch_bounds__(256) void edge_kernel(
    const float* __restrict__ ea,
    const int* __restrict__ eidx,
    const float* __restrict__ We,
    const float* __restrict__ be,
    float* __restrict__ wV)
{
    __shared__ float As[BK][BM + 1];         //  4.16 KB
    __shared__ float Bs[BK][BN];             //  8.00 KB
    __shared__ float Es[BM][BN + 4];         // 33.79 KB (padded rows, 16B-aligned stride)
    __shared__ float score_s[BM][NUM_HEADS]; //  2.00 KB
    __shared__ int src_s[BM], dst_s[BM];     //  0.50 KB

    const int tid = threadIdx.x;
    const int e0 = blockIdx.x * BM;

    if (tid < BM) {
        src_s[tid] = eidx[e0 + tid];
        dst_s[tid] = eidx[N_EDGES + e0 + tid];
    }
    // covered by first __syncthreads inside gemm64x128

    float acc[4][8];
    gemm64x128(ea, We, be, e0, N_EDGES, false, acc, As, Bs);

    const int tx = tid & 15;
    const int ty = tid >> 4;

    // stash E tile in shared
#pragma unroll
    for (int i = 0; i < 4; i++) {
        float* e = &Es[ty * 4 + i][tx * 8];
        *(float4*)(e + 0) = make_float4(acc[i][0], acc[i][1], acc[i][2], acc[i][3]);
        *(float4*)(e + 4) = make_float4(acc[i][4], acc[i][5], acc[i][6], acc[i][7]);
    }
    __syncthreads();

    // scores: 64 edges x 8 heads = 512 pairs
#pragma unroll
    for (int p = tid; p < BM * NUM_HEADS; p += 256) {
        int m = p >> 3;
        int h = p & 7;
        const float* kr = gK + (size_t)src_s[m] * DIM + h * HEAD_DIM;
        const float* qr = gQ + (size_t)dst_s[m] * DIM + h * HEAD_DIM;
        const float* er = &Es[m][h * HEAD_DIM];
        float s = 0.f;
#pragma unroll
        for (int j = 0; j < HEAD_DIM; j += 4) {
            float4 kv = *(const float4*)(kr + j);
            float4 qv = *(const float4*)(qr + j);
            float4 ev = *(const float4*)(er + j);
            s += kv.x * qv.x * ev.x + kv.y * qv.y * ev.y
               + kv.z * qv.z * ev.z + kv.w * qv.w * ev.w;
        }
        s *= 0.25f;  // 1/sqrt(HEAD_DIM=16)
        s = fminf(fmaxf(s, -5.f), 5.f);
        score_s[m][h] = expf(s);
    }
    __syncthreads();

    // Z reductions: 64 edges x 2 float4
    if (tid < BM * 2) {
        int m = tid >> 1;
        int hh = (tid & 1) * 4;
        float4 sv = *(float4*)&score_s[m][hh];
        red_add_v4(&gZ[(size_t)dst_s[m] * NUM_HEADS + hh], sv);
    }

    // messages: 64 edges x 32 float4 of V, scaled by per-head score
#pragma unroll
    for (int it = tid; it < BM * 32; it += 256) {
        int m = it >> 5;
        int c4 = it & 31;
        float4 vv = *(const float4*)(gV + (size_t)src_s[m] * DIM + c4 * 4);
        float sc = score_s[m][c4 >> 2];
        vv.x *= sc; vv.y *= sc; vv.z *= sc; vv.w *= sc;
        red_add_v4(wV + (size_t)dst_s[m] * DIM + c4 * 4, vv);
    }
}

// ---------------------------------------------------------------------------
// Finalize: out = wV / (Z + 1e-6)
// ---------------------------------------------------------------------------
__global__ void finalize_kernel(float* __restrict__ out) {
    int i = blockIdx.x * blockDim.x + threadIdx.x;
    if (i >= N_NODES * 32) return;
    int n = i >> 5;
    int c4 = i & 31;
    float* p = out + (size_t)n * DIM + c4 * 4;
    float4 v = *(float4*)p;
    float inv = 1.f / (gZ[n * NUM_HEADS + (c4 >> 2)] + 1e-6f);
    v.x *= inv; v.y *= inv; v.z *= inv; v.w *= inv;
    *(float4*)p = v;
}

// ---------------------------------------------------------------------------
extern "C" void kernel_launch(void* const* d_in, const int* in_sizes, int n_in,
                              void* d_out, int out_size)
{
    const float* x  = (const float*)d_in[0];
    const float* ea = (const float*)d_in[1];
    const int* eidx = (const int*)d_in[2];
    const float* Wq = (const float*)d_in[3];
    const float* bq = (const float*)d_in[4];
    const float* Wk = (const float*)d_in[5];
    const float* bk = (const float*)d_in[6];
    const float* We = (const float*)d_in[7];
    const float* be = (const float*)d_in[8];
    const float* Wv = (const float*)d_in[9];
    const float* bv = (const float*)d_in[10];
    float* out = (float*)d_out;

    zero_kernel<<<(N_NODES * DIM + 255) / 256, 256>>>(out);

    dim3 gqkv((N_NODES + BM - 1) / BM, 1, 3);
    qkv_kernel<<<gqkv, 256>>>(x, Wq, bq, Wk, bk, Wv, bv);

    edge_kernel<<<N_EDGES / BM, 256>>>(ea, eidx, We, be, out);

    finalize_kernel<<<(N_NODES * 32 + 255) / 256, 256>>>(out);
}

// round 11
// speedup vs baseline: 1.8620x; 1.8620x over previous
#include <cstdint>
#include <stdint.h>
#include <cuda_runtime.h>
#include <cuda_bf16.h>
#include <math.h>

using std::uint32_t;
using std::uint64_t;

#define N_NODES 50000
#define N_EDGES 800000
#define DIM 128
#define NUM_HEADS 8
#define HEAD_DIM 16

// fp32 SIMT GEMM tiling (QKV projections)
#define BM 64
#define BK 16
#define BN 128

// edge kernel (HMMA path)
#define EBM 128            // edges per block
#define KCHUNK 64          // k per SMEM chunk
#define NCHUNK 2
#define ASTRIDE 72         // halves per row in SMEM tiles (bank-conflict-free: 36 words)
#define ESTRIDE 132        // floats per row of E spill tile

// Scratch (static device globals -- allocation-free per harness rules)
__device__ float gQ[N_NODES * DIM];
__device__ float gK[N_NODES * DIM];
__device__ float gV[N_NODES * DIM];
__device__ float gZ[N_NODES * NUM_HEADS];
__device__ __nv_bfloat16 gWeTh[DIM * DIM];   // We^T hi split, [n][k]
__device__ __nv_bfloat16 gWeTl[DIM * DIM];   // We^T lo split, [n][k]

// ---------------------------------------------------------------------------
// helpers
// ---------------------------------------------------------------------------
__device__ __forceinline__ uint32_t smem_u32(const void* p) {
    uint32_t a;
    asm("{ .reg .u64 t; cvta.to.shared.u64 t, %1; cvt.u32.u64 %0, t; }"
        : "=r"(a) : "l"(p));
    return a;
}

__device__ __forceinline__ uint32_t lds32(uint32_t addr) {
    uint32_t v;
    asm volatile("ld.shared.b32 %0, [%1];" : "=r"(v) : "r"(addr));
    return v;
}

__device__ __forceinline__ void red_add_v4(float* addr, float4 v) {
    asm volatile("red.global.add.v4.f32 [%0], {%1,%2,%3,%4};"
                 :: "l"(addr), "f"(v.x), "f"(v.y), "f"(v.z), "f"(v.w)
                 : "memory");
}

// m16n8k16 bf16 HMMA, fp32 accumulate (base sm_80+ PTX -- no 'a' features)
__device__ __forceinline__ void mma16816(float (&d)[4],
                                         const uint32_t (&a)[4],
                                         uint32_t b0, uint32_t b1) {
    asm volatile(
        "mma.sync.aligned.m16n8k16.row.col.f32.bf16.bf16.f32 "
        "{%0,%1,%2,%3}, {%4,%5,%6,%7}, {%8,%9}, {%0,%1,%2,%3};"
        : "+f"(d[0]), "+f"(d[1]), "+f"(d[2]), "+f"(d[3])
        : "r"(a[0]), "r"(a[1]), "r"(a[2]), "r"(a[3]), "r"(b0), "r"(b1));
}

// ---------------------------------------------------------------------------
// Prep: split We^T into hi/lo bf16 (tiny, once per launch)
// ---------------------------------------------------------------------------
__global__ void prep_kernel(const float* __restrict__ We) {
    int i = blockIdx.x * blockDim.x + threadIdx.x;
    if (i >= DIM * DIM) return;
    int n = i >> 7, k = i & 127;
    float w = We[k * DIM + n];
    __nv_bfloat16 h = __float2bfloat16_rn(w);
    float lo = w - __bfloat162float(h);
    gWeTh[n * DIM + k] = h;
    gWeTl[n * DIM + k] = __float2bfloat16_rn(lo);
}

// ---------------------------------------------------------------------------
// Zero init: d_out (wV accumulator) and gZ
// ---------------------------------------------------------------------------
__global__ void zero_kernel(float* __restrict__ out) {
    int i = blockIdx.x * blockDim.x + threadIdx.x;
    if (i < N_NODES * DIM) out[i] = 0.f;
    if (i < N_NODES * NUM_HEADS) gZ[i] = 0.f;
}

// ---------------------------------------------------------------------------
// 64x128 fp32 GEMM tile (QKV path, unchanged)
// ---------------------------------------------------------------------------
__device__ __forceinline__ void gemm64x128(
    const float* __restrict__ A,
    const float* __restrict__ W,
    const float* __restrict__ bias,
    int row0, int M, bool guard,
    float (&acc)[4][8],
    float (*As)[BM + 1],
    float (*Bs)[BN])
{
    const int tid = threadIdx.x;
    const int tx = tid & 15;
    const int ty = tid >> 4;

#pragma unroll
    for (int i = 0; i < 4; i++)
#pragma unroll
        for (int j = 0; j < 8; j++) acc[i][j] = 0.f;

    for (int k0 = 0; k0 < DIM; k0 += BK) {
        {
            int idx = tid * 4;
            int m = idx >> 4;
            int k = idx & 15;
            float4 a;
            int grow = row0 + m;
            if (!guard || grow < M)
                a = *(const float4*)(A + (size_t)grow * DIM + k0 + k);
            else
                a = make_float4(0.f, 0.f, 0.f, 0.f);
            As[k + 0][m] = a.x;
            As[k + 1][m] = a.y;
            As[k + 2][m] = a.z;
            As[k + 3][m] = a.w;
        }
        {
#pragma unroll
            for (int r = 0; r < 2; r++) {
                int idx = tid * 8 + r * 4;
                int k = idx >> 7;
                int n = idx & 127;
                *(float4*)&Bs[k][n] = *(const float4*)(W + (size_t)(k0 + k) * DIM + n);
            }
        }
        __syncthreads();

#pragma unroll
        for (int k = 0; k < BK; k++) {
            float a[4], b[8];
#pragma unroll
            for (int i = 0; i < 4; i++) a[i] = As[k][ty * 4 + i];
#pragma unroll
            for (int j = 0; j < 8; j++) b[j] = Bs[k][tx * 8 + j];
#pragma unroll
            for (int i = 0; i < 4; i++)
#pragma unroll
                for (int j = 0; j < 8; j++) acc[i][j] += a[i] * b[j];
        }
        __syncthreads();
    }

#pragma unroll
    for (int j = 0; j < 8; j++) {
        float bv = bias[tx * 8 + j];
#pragma unroll
        for (int i = 0; i < 4; i++) acc[i][j] += bv;
    }
}

// ---------------------------------------------------------------------------
// QKV projections (fp32 SIMT, unchanged this round)
// ---------------------------------------------------------------------------
__global__ __launch_bounds__(256) void qkv_kernel(
    const float* __restrict__ x,
    const float* __restrict__ Wq, const float* __restrict__ bq,
    const float* __restrict__ Wk, const float* __restrict__ bk,
    const float* __restrict__ Wv, const float* __restrict__ bv)
{
    __shared__ float As[BK][BM + 1];
    __shared__ float Bs[BK][BN];

    const float* W;
    const float* b;
    float* out;
    if (blockIdx.z == 0)      { W = Wq; b = bq; out = gQ; }
    else if (blockIdx.z == 1) { W = Wk; b = bk; out = gK; }
    else                      { W = Wv; b = bv; out = gV; }

    int row0 = blockIdx.x * BM;
    float acc[4][8];
    gemm64x128(x, W, b, row0, N_NODES, true, acc, As, Bs);

    const int tid = threadIdx.x;
    const int tx = tid & 15;
    const int ty = tid >> 4;

#pragma unroll
    for (int i = 0; i < 4; i++) {
        int r = row0 + ty * 4 + i;
        if (r < N_NODES) {
            float* o = out + (size_t)r * DIM + tx * 8;
            *(float4*)(o + 0) = make_float4(acc[i][0], acc[i][1], acc[i][2], acc[i][3]);
            *(float4*)(o + 4) = make_float4(acc[i][4], acc[i][5], acc[i][6], acc[i][7]);
        }
    }
}

// ---------------------------------------------------------------------------
// Fused edge kernel, HMMA (mma.sync bf16x3) E-GEMM:
//   E tile (128 edges x 128 dims) = ea_tile @ We, fp32 accum in registers,
//   spilled to SMEM; then proven score/atomic epilogue.
// Dyn smem layout (73,728 B), two overlapping uses:
//   GEMM phase:  sAh[128][72]h | sAl | sBh[128][72]h | sBl   (4 x 18,432 B)
//   Epilogue:    Es[128][132] float                          (67,584 B)
// ---------------------------------------------------------------------------
#define TILE_BYTES (EBM * ASTRIDE * 2)          // 18,432
#define EDGE_DYN_SMEM (4 * TILE_BYTES)          // 73,728

__global__ __launch_bounds__(256, 2)
void edge_kernel(const float* __restrict__ ea,
                 const int* __restrict__ eidx,
                 const float* __restrict__ be,
                 float* __restrict__ wV)
{
    extern __shared__ char dyn_smem[];
    __shared__ int src_s[EBM], dst_s[EBM];
    __shared__ float score_s[EBM][NUM_HEADS];

    const int tid = threadIdx.x;
    const int warp = tid >> 5;
    const int lane = tid & 31;
    const int e0 = blockIdx.x * EBM;

    const uint32_t base = smem_u32(dyn_smem);
    const uint32_t sAh = base;
    const uint32_t sAl = base + TILE_BYTES;
    const uint32_t sBh = base + 2 * TILE_BYTES;
    const uint32_t sBl = base + 3 * TILE_BYTES;

    if (tid < EBM) {
        src_s[tid] = eidx[e0 + tid];
        dst_s[tid] = eidx[N_EDGES + e0 + tid];
    }

    const int g = lane >> 2;          // 0..7
    const int cc = lane & 3;          // 0..3
    const int m0 = warp * 16;         // warp's row base

    float acc[16][4];
#pragma unroll
    for (int nt = 0; nt < 16; nt++)
#pragma unroll
        for (int j = 0; j < 4; j++) acc[nt][j] = 0.f;

    for (int c = 0; c < NCHUNK; c++) {
        if (c > 0) __syncthreads();   // all warps done reading previous chunk

        // --- A tile: ea rows e0..e0+127, cols [c*64, c*64+64), hi/lo split ---
        for (int i = tid; i < EBM * (KCHUNK / 4); i += 256) {
            int row = i >> 4, q = i & 15;
            float4 v = *(const float4*)(ea + (size_t)(e0 + row) * DIM + c * KCHUNK + q * 4);
            __nv_bfloat162 h01 = __float22bfloat162_rn(make_float2(v.x, v.y));
            __nv_bfloat162 h23 = __float22bfloat162_rn(make_float2(v.z, v.w));
            float2 r01 = make_float2(v.x - __bfloat162float(__low2bfloat16(h01)),
                                     v.y - __bfloat162float(__high2bfloat16(h01)));
            float2 r23 = make_float2(v.z - __bfloat162float(__low2bfloat16(h23)),
                                     v.w - __bfloat162float(__high2bfloat16(h23)));
            __nv_bfloat162 l01 = __float22bfloat162_rn(r01);
            __nv_bfloat162 l23 = __float22bfloat162_rn(r23);
            uint32_t hp0 = *(uint32_t*)&h01, hp1 = *(uint32_t*)&h23;
            uint32_t lp0 = *(uint32_t*)&l01, lp1 = *(uint32_t*)&l23;
            uint32_t off = (uint32_t)(row * ASTRIDE + q * 4) * 2;   // bytes
            asm volatile("st.shared.v2.b32 [%0], {%1,%2};"
                         :: "r"(sAh + off), "r"(hp0), "r"(hp1) : "memory");
            asm volatile("st.shared.v2.b32 [%0], {%1,%2};"
                         :: "r"(sAl + off), "r"(lp0), "r"(lp1) : "memory");
        }
        // --- B tile: We^T splits, rows n=0..127, cols [c*64, c*64+64) ---
        for (int i = tid; i < DIM * 8; i += 256) {
            int row = i >> 3, q = i & 7;
            uint4 hv = *(const uint4*)(gWeTh + row * DIM + c * KCHUNK + q * 8);
            uint4 lv = *(const uint4*)(gWeTl + row * DIM + c * KCHUNK + q * 8);
            uint32_t off = (uint32_t)(row * ASTRIDE + q * 8) * 2;   // bytes
            asm volatile("st.shared.v4.b32 [%0], {%1,%2,%3,%4};"
                         :: "r"(sBh + off), "r"(hv.x), "r"(hv.y), "r"(hv.z), "r"(hv.w)
                         : "memory");
            asm volatile("st.shared.v4.b32 [%0], {%1,%2,%3,%4};"
                         :: "r"(sBl + off), "r"(lv.x), "r"(lv.y), "r"(lv.z), "r"(lv.w)
                         : "memory");
        }
        __syncthreads();

        // --- MMA mainloop: 4 k-steps of 16 ---
#pragma unroll
        for (int ks = 0; ks < 4; ks++) {
            const uint32_t a00 = (uint32_t)((m0 + g) * ASTRIDE + ks * 16 + cc * 2) * 2;
            uint32_t ah[4], al[4];
            ah[0] = lds32(sAh + a00);
            ah[1] = lds32(sAh + a00 + 8 * ASTRIDE * 2);
            ah[2] = lds32(sAh + a00 + 16);
            ah[3] = lds32(sAh + a00 + 8 * ASTRIDE * 2 + 16);
            al[0] = lds32(sAl + a00);
            al[1] = lds32(sAl + a00 + 8 * ASTRIDE * 2);
            al[2] = lds32(sAl + a00 + 16);
            al[3] = lds32(sAl + a00 + 8 * ASTRIDE * 2 + 16);
#pragma unroll
            for (int nt = 0; nt < 16; nt++) {
                const uint32_t b0 = (uint32_t)((nt * 8 + g) * ASTRIDE + ks * 16 + cc * 2) * 2;
                uint32_t bh0 = lds32(sBh + b0);
                uint32_t bh1 = lds32(sBh + b0 + 16);
                uint32_t bl0 = lds32(sBl + b0);
                uint32_t bl1 = lds32(sBl + b0 + 16);
                mma16816(acc[nt], ah, bh0, bh1);   // Ah*Bh
                mma16816(acc[nt], ah, bl0, bl1);   // Ah*Bl
                mma16816(acc[nt], al, bh0, bh1);   // Al*Bh
            }
        }
    }

    __syncthreads();   // all warps done reading tiles before Es overwrite

    // --- spill E accumulators to SMEM: Es[128][132] floats ---
    {
        float* Es = (float*)dyn_smem;
#pragma unroll
        for (int nt = 0; nt < 16; nt++) {
            int col = nt * 8 + cc * 2;
            *(float2*)&Es[(m0 + g) * ESTRIDE + col]     = make_float2(acc[nt][0], acc[nt][1]);
            *(float2*)&Es[(m0 + g + 8) * ESTRIDE + col] = make_float2(acc[nt][2], acc[nt][3]);
        }
    }
    __syncthreads();

    // --- scores: 128 edges x 8 heads = 1024 pairs (proven R3 epilogue) ---
    {
        const float* Es = (const float*)dyn_smem;
#pragma unroll
        for (int p = tid; p < EBM * NUM_HEADS; p += 256) {
            int m = p >> 3;
            int h = p & 7;
            const float* kr = gK + (size_t)src_s[m] * DIM + h * HEAD_DIM;
            const float* qr = gQ + (size_t)dst_s[m] * DIM + h * HEAD_DIM;
            const float* er = Es + m * ESTRIDE + h * HEAD_DIM;
            float s = 0.f;
#pragma unroll
            for (int j = 0; j < HEAD_DIM; j += 4) {
                float4 kv = *(const float4*)(kr + j);
                float4 qv = *(const float4*)(qr + j);
                float4 ev = *(const float4*)(er + j);
                float4 bv = *(const float4*)(be + h * HEAD_DIM + j);
                s += kv.x * qv.x * (ev.x + bv.x);
                s += kv.y * qv.y * (ev.y + bv.y);
                s += kv.z * qv.z * (ev.z + bv.z);
                s += kv.w * qv.w * (ev.w + bv.w);
            }
            s *= 0.25f;  // 1/sqrt(HEAD_DIM=16)
            s = fminf(fmaxf(s, -5.f), 5.f);
            score_s[m][h] = expf(s);
        }
    }
    __syncthreads();

    // Z reductions: 128 edges x 2 float4 = 256 ops
    {
        int mm = tid >> 1;
        int hh4 = (tid & 1) * 4;
        float4 sv = *(float4*)&score_s[mm][hh4];
        red_add_v4(&gZ[(size_t)dst_s[mm] * NUM_HEADS + hh4], sv);
    }

    // messages: 128 edges x 32 float4 of V, scaled per-head
#pragma unroll
    for (int it = tid; it < EBM * 32; it += 256) {
        int mm = it >> 5;
        int c4 = it & 31;
        float4 vv = *(const float4*)(gV + (size_t)src_s[mm] * DIM + c4 * 4);
        float sc = score_s[mm][c4 >> 2];
        vv.x *= sc; vv.y *= sc; vv.z *= sc; vv.w *= sc;
        red_add_v4(wV + (size_t)dst_s[mm] * DIM + c4 * 4, vv);
    }
}

// ---------------------------------------------------------------------------
// Finalize: out = wV / (Z + 1e-6)
// ---------------------------------------------------------------------------
__global__ void finalize_kernel(float* __restrict__ out) {
    int i = blockIdx.x * blockDim.x + threadIdx.x;
    if (i >= N_NODES * 32) return;
    int n = i >> 5;
    int c4 = i & 31;
    float* p = out + (size_t)n * DIM + c4 * 4;
    float4 v = *(float4*)p;
    float inv = 1.f / (gZ[n * NUM_HEADS + (c4 >> 2)] + 1e-6f);
    v.x *= inv; v.y *= inv; v.z *= inv; v.w *= inv;
    *(float4*)p = v;
}

// ---------------------------------------------------------------------------
extern "C" void kernel_launch(void* const* d_in, const int* in_sizes, int n_in,
                              void* d_out, int out_size)
{
    const float* x  = (const float*)d_in[0];
    const float* ea = (const float*)d_in[1];
    const int* eidx = (const int*)d_in[2];
    const float* Wq = (const float*)d_in[3];
    const float* bq = (const float*)d_in[4];
    const float* Wk = (const float*)d_in[5];
    const float* bk = (const float*)d_in[6];
    const float* We = (const float*)d_in[7];
    const float* be = (const float*)d_in[8];
    const float* Wv = (const float*)d_in[9];
    const float* bv = (const float*)d_in[10];
    float* out = (float*)d_out;

    cudaFuncSetAttribute(edge_kernel,
                         cudaFuncAttributeMaxDynamicSharedMemorySize, EDGE_DYN_SMEM);

    prep_kernel<<<(DIM * DIM + 255) / 256, 256>>>(We);

    zero_kernel<<<(N_NODES * DIM + 255) / 256, 256>>>(out);

    dim3 gqkv((N_NODES + BM - 1) / BM, 1, 3);
    qkv_kernel<<<gqkv, 256>>>(x, Wq, bq, Wk, bk, Wv, bv);

    edge_kernel<<<N_EDGES / EBM, 256, EDGE_DYN_SMEM>>>(ea, eidx, be, out);

    finalize_kernel<<<(N_NODES * 32 + 255) / 256, 256>>>(out);
}

// round 12
// speedup vs baseline: 2.3309x; 1.2518x over previous
#include <cstdint>
#include <stdint.h>
#include <cuda_runtime.h>
#include <cuda_bf16.h>
#include <math.h>

using std::uint32_t;
using std::uint64_t;

#define N_NODES 50000
#define N_EDGES 800000
#define DIM 128
#define NUM_HEADS 8
#define HEAD_DIM 16

// HMMA GEMM tiling (both edge-E and QKV paths)
#define EBM 128            // rows per block
#define KCHUNK 64          // k per SMEM chunk
#define NCHUNK 2
#define ASTRIDE 72         // halves per row in SMEM tiles (36 words: ldsm conflict-free)
#define ESTRIDE 132        // floats per row of E spill tile

#define TILE_BYTES (EBM * ASTRIDE * 2)          // 18,432
#define GEMM_DYN_SMEM (4 * TILE_BYTES)          // 73,728

// Scratch (static device globals -- allocation-free per harness rules)
__device__ float gQ[N_NODES * DIM];
__device__ float gK[N_NODES * DIM];
__device__ float gV[N_NODES * DIM];
__device__ float gZ[N_NODES * NUM_HEADS];
// W^T hi/lo bf16 splits, [n][k]; index 0=We, 1=Wq, 2=Wk, 3=Wv
__device__ __nv_bfloat16 gWTh[4][DIM * DIM];
__device__ __nv_bfloat16 gWTl[4][DIM * DIM];

// ---------------------------------------------------------------------------
// helpers
// ---------------------------------------------------------------------------
__device__ __forceinline__ uint32_t smem_u32(const void* p) {
    uint32_t a;
    asm("{ .reg .u64 t; cvta.to.shared.u64 t, %1; cvt.u32.u64 %0, t; }"
        : "=r"(a) : "l"(p));
    return a;
}

__device__ __forceinline__ void red_add_v4(float* addr, float4 v) {
    asm volatile("red.global.add.v4.f32 [%0], {%1,%2,%3,%4};"
                 :: "l"(addr), "f"(v.x), "f"(v.y), "f"(v.z), "f"(v.w)
                 : "memory");
}

__device__ __forceinline__ void ldsm_x4(uint32_t (&r)[4], uint32_t addr) {
    asm volatile("ldmatrix.sync.aligned.m8n8.x4.shared.b16 {%0,%1,%2,%3}, [%4];"
                 : "=r"(r[0]), "=r"(r[1]), "=r"(r[2]), "=r"(r[3]) : "r"(addr));
}

// m16n8k16 bf16 HMMA, fp32 accumulate (base sm_80+ PTX)
__device__ __forceinline__ void mma16816(float (&d)[4],
                                         const uint32_t* a,
                                         uint32_t b0, uint32_t b1) {
    asm volatile(
        "mma.sync.aligned.m16n8k16.row.col.f32.bf16.bf16.f32 "
        "{%0,%1,%2,%3}, {%4,%5,%6,%7}, {%8,%9}, {%0,%1,%2,%3};"
        : "+f"(d[0]), "+f"(d[1]), "+f"(d[2]), "+f"(d[3])
        : "r"(a[0]), "r"(a[1]), "r"(a[2]), "r"(a[3]), "r"(b0), "r"(b1));
}

// ---------------------------------------------------------------------------
// Prep: split all four W^T into hi/lo bf16 (tiny, once per launch)
// ---------------------------------------------------------------------------
__global__ void prep_kernel(const float* __restrict__ We,
                            const float* __restrict__ Wq,
                            const float* __restrict__ Wk,
                            const float* __restrict__ Wv) {
    int i = blockIdx.x * blockDim.x + threadIdx.x;
    if (i >= 4 * DIM * DIM) return;
    int iw = i >> 14;
    int rem = i & 16383;
    int n = rem >> 7, k = rem & 127;
    const float* W = (iw == 0) ? We : (iw == 1) ? Wq : (iw == 2) ? Wk : Wv;
    float w = W[k * DIM + n];
    __nv_bfloat16 h = __float2bfloat16_rn(w);
    float lo = w - __bfloat162float(h);
    gWTh[iw][n * DIM + k] = h;
    gWTl[iw][n * DIM + k] = __float2bfloat16_rn(lo);
}

// ---------------------------------------------------------------------------
// Zero init: d_out (wV accumulator) and gZ
// ---------------------------------------------------------------------------
__global__ void zero_kernel(float* __restrict__ out) {
    int i = blockIdx.x * blockDim.x + threadIdx.x;
    if (i < N_NODES * DIM) out[i] = 0.f;
    if (i < N_NODES * NUM_HEADS) gZ[i] = 0.f;
}

// ---------------------------------------------------------------------------
// Shared GEMM building blocks (128 rows x 128 cols, bf16x3 split precision)
// Warp grid 4x2: warp (wm = warp&3, wn = warp>>2) owns rows [wm*32,+32) x
// cols [wn*64,+64).  acc[mt 2][nt 8][4].
// ---------------------------------------------------------------------------
__device__ __forceinline__ void fill_A_chunk(
    const float* __restrict__ A, int row0, bool guard, int c,
    uint32_t sAh, uint32_t sAl, int tid)
{
    for (int i = tid; i < EBM * (KCHUNK / 4); i += 256) {
        int row = i >> 4, q = i & 15;
        int grow = row0 + row;
        float4 v = make_float4(0.f, 0.f, 0.f, 0.f);
        if (!guard || grow < N_NODES)
            v = *(const float4*)(A + (size_t)grow * DIM + c * KCHUNK + q * 4);
        __nv_bfloat162 h01 = __float22bfloat162_rn(make_float2(v.x, v.y));
        __nv_bfloat162 h23 = __float22bfloat162_rn(make_float2(v.z, v.w));
        float2 r01 = make_float2(v.x - __bfloat162float(__low2bfloat16(h01)),
                                 v.y - __bfloat162float(__high2bfloat16(h01)));
        float2 r23 = make_float2(v.z - __bfloat162float(__low2bfloat16(h23)),
                                 v.w - __bfloat162float(__high2bfloat16(h23)));
        __nv_bfloat162 l01 = __float22bfloat162_rn(r01);
        __nv_bfloat162 l23 = __float22bfloat162_rn(r23);
        uint32_t hp0 = *(uint32_t*)&h01, hp1 = *(uint32_t*)&h23;
        uint32_t lp0 = *(uint32_t*)&l01, lp1 = *(uint32_t*)&l23;
        uint32_t off = (uint32_t)(row * ASTRIDE + q * 4) * 2;   // bytes
        asm volatile("st.shared.v2.b32 [%0], {%1,%2};"
                     :: "r"(sAh + off), "r"(hp0), "r"(hp1) : "memory");
        asm volatile("st.shared.v2.b32 [%0], {%1,%2};"
                     :: "r"(sAl + off), "r"(lp0), "r"(lp1) : "memory");
    }
}

__device__ __forceinline__ void fill_B_chunk(
    const __nv_bfloat16* __restrict__ Wh, const __nv_bfloat16* __restrict__ Wl,
    int c, uint32_t sBh, uint32_t sBl, int tid)
{
    for (int i = tid; i < DIM * 8; i += 256) {
        int row = i >> 3, q = i & 7;
        uint4 hv = *(const uint4*)(Wh + row * DIM + c * KCHUNK + q * 8);
        uint4 lv = *(const uint4*)(Wl + row * DIM + c * KCHUNK + q * 8);
        uint32_t off = (uint32_t)(row * ASTRIDE + q * 8) * 2;   // bytes
        asm volatile("st.shared.v4.b32 [%0], {%1,%2,%3,%4};"
                     :: "r"(sBh + off), "r"(hv.x), "r"(hv.y), "r"(hv.z), "r"(hv.w)
                     : "memory");
        asm volatile("st.shared.v4.b32 [%0], {%1,%2,%3,%4};"
                     :: "r"(sBl + off), "r"(lv.x), "r"(lv.y), "r"(lv.z), "r"(lv.w)
                     : "memory");
    }
}

// MMA mainloop over one k-chunk; warp-tiled 32x64; ldmatrix fragment loads.
__device__ __forceinline__ void mma_chunk(
    float (&acc)[2][8][4],
    uint32_t sAh, uint32_t sAl, uint32_t sBh, uint32_t sBl,
    int warp, int lane)
{
    const int wm = warp & 3;
    const int wn = warp >> 2;
    const int t8 = lane & 7;
    const int sel = lane >> 3;

#pragma unroll
    for (int ks = 0; ks < 4; ks++) {
        uint32_t ah[2][4], al[2][4];
#pragma unroll
        for (int mt = 0; mt < 2; mt++) {
            // tiles: {(m,k),(m+8,k),(m,k+8),(m+8,k+8)}
            uint32_t arow = (uint32_t)(wm * 32 + mt * 16 + t8 + (sel & 1) * 8);
            uint32_t acol = (uint32_t)(ks * 16 + (sel >> 1) * 8);
            uint32_t aoff = (arow * ASTRIDE + acol) * 2;
            ldsm_x4(ah[mt], sAh + aoff);
            ldsm_x4(al[mt], sAl + aoff);
        }
#pragma unroll
        for (int nb = 0; nb < 4; nb++) {
            // tiles: {(n,k),(n,k+8),(n+8,k),(n+8,k+8)} = {nt0.b0, nt0.b1, nt1.b0, nt1.b1}
            uint32_t brow = (uint32_t)(wn * 64 + nb * 16 + t8 + (sel >> 1) * 8);
            uint32_t bcol = (uint32_t)(ks * 16 + (sel & 1) * 8);
            uint32_t boff = (brow * ASTRIDE + bcol) * 2;
            uint32_t bh[4], bl[4];
            ldsm_x4(bh, sBh + boff);
            ldsm_x4(bl, sBl + boff);
#pragma unroll
            for (int mt = 0; mt < 2; mt++) {
#pragma unroll
                for (int nn = 0; nn < 2; nn++) {
                    float (&d)[4] = acc[mt][nb * 2 + nn];
                    mma16816(d, ah[mt], bh[nn * 2], bh[nn * 2 + 1]);  // Ah*Bh
                    mma16816(d, ah[mt], bl[nn * 2], bl[nn * 2 + 1]);  // Ah*Bl
                    mma16816(d, al[mt], bh[nn * 2], bh[nn * 2 + 1]);  // Al*Bh
                }
            }
        }
    }
}

// ---------------------------------------------------------------------------
// QKV projections on the HMMA path: grid (ceil(N/128), 1, 3)
// ---------------------------------------------------------------------------
__global__ __launch_bounds__(256, 2)
void qkv_kernel(const float* __restrict__ x,
                const float* __restrict__ bq,
                const float* __restrict__ bk,
                const float* __restrict__ bv)
{
    extern __shared__ char dyn_smem[];
    const int tid = threadIdx.x;
    const int warp = tid >> 5;
    const int lane = tid & 31;
    const int row0 = blockIdx.x * EBM;
    const int z = blockIdx.z;

    const __nv_bfloat16* Wh = gWTh[z + 1];
    const __nv_bfloat16* Wl = gWTl[z + 1];
    const float* bias = (z == 0) ? bq : (z == 1) ? bk : bv;
    float* out = (z == 0) ? gQ : (z == 1) ? gK : gV;

    const uint32_t base = smem_u32(dyn_smem);
    const uint32_t sAh = base;
    const uint32_t sAl = base + TILE_BYTES;
    const uint32_t sBh = base + 2 * TILE_BYTES;
    const uint32_t sBl = base + 3 * TILE_BYTES;

    float acc[2][8][4];
#pragma unroll
    for (int mt = 0; mt < 2; mt++)
#pragma unroll
        for (int nt = 0; nt < 8; nt++)
#pragma unroll
            for (int j = 0; j < 4; j++) acc[mt][nt][j] = 0.f;

    for (int c = 0; c < NCHUNK; c++) {
        if (c > 0) __syncthreads();
        fill_A_chunk(x, row0, true, c, sAh, sAl, tid);
        fill_B_chunk(Wh, Wl, c, sBh, sBl, tid);
        __syncthreads();
        mma_chunk(acc, sAh, sAl, sBh, sBl, warp, lane);
    }

    // store with bias
    const int wm = warp & 3, wn = warp >> 2;
    const int g = lane >> 2, cc = lane & 3;
#pragma unroll
    for (int mt = 0; mt < 2; mt++) {
#pragma unroll
        for (int nt = 0; nt < 8; nt++) {
            int col = wn * 64 + nt * 8 + cc * 2;
            float b0 = bias[col], b1 = bias[col + 1];
            int r0 = row0 + wm * 32 + mt * 16 + g;
            if (r0 < N_NODES)
                *(float2*)(out + (size_t)r0 * DIM + col) =
                    make_float2(acc[mt][nt][0] + b0, acc[mt][nt][1] + b1);
            if (r0 + 8 < N_NODES)
                *(float2*)(out + (size_t)(r0 + 8) * DIM + col) =
                    make_float2(acc[mt][nt][2] + b0, acc[mt][nt][3] + b1);
        }
    }
}

// ---------------------------------------------------------------------------
// Fused edge kernel: HMMA E-GEMM + score/atomic epilogue
// ---------------------------------------------------------------------------
__global__ __launch_bounds__(256, 2)
void edge_kernel(const float* __restrict__ ea,
                 const int* __restrict__ eidx,
                 const float* __restrict__ be,
                 float* __restrict__ wV)
{
    extern __shared__ char dyn_smem[];
    __shared__ int src_s[EBM], dst_s[EBM];
    __shared__ float score_s[EBM][NUM_HEADS];

    const int tid = threadIdx.x;
    const int warp = tid >> 5;
    const int lane = tid & 31;
    const int e0 = blockIdx.x * EBM;

    const uint32_t base = smem_u32(dyn_smem);
    const uint32_t sAh = base;
    const uint32_t sAl = base + TILE_BYTES;
    const uint32_t sBh = base + 2 * TILE_BYTES;
    const uint32_t sBl = base + 3 * TILE_BYTES;

    if (tid < EBM) {
        src_s[tid] = eidx[e0 + tid];
        dst_s[tid] = eidx[N_EDGES + e0 + tid];
    }

    float acc[2][8][4];
#pragma unroll
    for (int mt = 0; mt < 2; mt++)
#pragma unroll
        for (int nt = 0; nt < 8; nt++)
#pragma unroll
            for (int j = 0; j < 4; j++) acc[mt][nt][j] = 0.f;

    for (int c = 0; c < NCHUNK; c++) {
        if (c > 0) __syncthreads();
        fill_A_chunk(ea, e0, false, c, sAh, sAl, tid);
        fill_B_chunk(gWTh[0], gWTl[0], c, sBh, sBl, tid);
        __syncthreads();
        mma_chunk(acc, sAh, sAl, sBh, sBl, warp, lane);
    }

    __syncthreads();   // all warps done reading tiles before Es overwrite

    // --- spill E accumulators to SMEM: Es[128][132] floats ---
    {
        float* Es = (float*)dyn_smem;
        const int wm = warp & 3, wn = warp >> 2;
        const int g = lane >> 2, cc = lane & 3;
#pragma unroll
        for (int mt = 0; mt < 2; mt++) {
#pragma unroll
            for (int nt = 0; nt < 8; nt++) {
                int row = wm * 32 + mt * 16 + g;
                int col = wn * 64 + nt * 8 + cc * 2;
                *(float2*)&Es[row * ESTRIDE + col] =
                    make_float2(acc[mt][nt][0], acc[mt][nt][1]);
                *(float2*)&Es[(row + 8) * ESTRIDE + col] =
                    make_float2(acc[mt][nt][2], acc[mt][nt][3]);
            }
        }
    }
    __syncthreads();

    // --- scores: 128 edges x 8 heads = 1024 pairs ---
    {
        const float* Es = (const float*)dyn_smem;
#pragma unroll
        for (int p = tid; p < EBM * NUM_HEADS; p += 256) {
            int m = p >> 3;
            int h = p & 7;
            const float* kr = gK + (size_t)src_s[m] * DIM + h * HEAD_DIM;
            const float* qr = gQ + (size_t)dst_s[m] * DIM + h * HEAD_DIM;
            const float* er = Es + m * ESTRIDE + h * HEAD_DIM;
            float s = 0.f;
#pragma unroll
            for (int j = 0; j < HEAD_DIM; j += 4) {
                float4 kv = *(const float4*)(kr + j);
                float4 qv = *(const float4*)(qr + j);
                float4 ev = *(const float4*)(er + j);
                float4 bv = *(const float4*)(be + h * HEAD_DIM + j);
                s += kv.x * qv.x * (ev.x + bv.x);
                s += kv.y * qv.y * (ev.y + bv.y);
                s += kv.z * qv.z * (ev.z + bv.z);
                s += kv.w * qv.w * (ev.w + bv.w);
            }
            s *= 0.25f;  // 1/sqrt(HEAD_DIM=16)
            s = fminf(fmaxf(s, -5.f), 5.f);
            score_s[m][h] = expf(s);
        }
    }
    __syncthreads();

    // Z reductions: 128 edges x 2 float4 = 256 ops
    {
        int mm = tid >> 1;
        int hh4 = (tid & 1) * 4;
        float4 sv = *(float4*)&score_s[mm][hh4];
        red_add_v4(&gZ[(size_t)dst_s[mm] * NUM_HEADS + hh4], sv);
    }

    // messages: 128 edges x 32 float4 of V, scaled per-head
#pragma unroll
    for (int it = tid; it < EBM * 32; it += 256) {
        int mm = it >> 5;
        int c4 = it & 31;
        float4 vv = *(const float4*)(gV + (size_t)src_s[mm] * DIM + c4 * 4);
        float sc = score_s[mm][c4 >> 2];
        vv.x *= sc; vv.y *= sc; vv.z *= sc; vv.w *= sc;
        red_add_v4(wV + (size_t)dst_s[mm] * DIM + c4 * 4, vv);
    }
}

// ---------------------------------------------------------------------------
// Finalize: out = wV / (Z + 1e-6)
// ---------------------------------------------------------------------------
__global__ void finalize_kernel(float* __restrict__ out) {
    int i = blockIdx.x * blockDim.x + threadIdx.x;
    if (i >= N_NODES * 32) return;
    int n = i >> 5;
    int c4 = i & 31;
    float* p = out + (size_t)n * DIM + c4 * 4;
    float4 v = *(float4*)p;
    float inv = 1.f / (gZ[n * NUM_HEADS + (c4 >> 2)] + 1e-6f);
    v.x *= inv; v.y *= inv; v.z *= inv; v.w *= inv;
    *(float4*)p = v;
}

// ---------------------------------------------------------------------------
extern "C" void kernel_launch(void* const* d_in, const int* in_sizes, int n_in,
                              void* d_out, int out_size)
{
    const float* x  = (const float*)d_in[0];
    const float* ea = (const float*)d_in[1];
    const int* eidx = (const int*)d_in[2];
    const float* Wq = (const float*)d_in[3];
    const float* bq = (const float*)d_in[4];
    const float* Wk = (const float*)d_in[5];
    const float* bk = (const float*)d_in[6];
    const float* We = (const float*)d_in[7];
    const float* be = (const float*)d_in[8];
    const float* Wv = (const float*)d_in[9];
    const float* bv = (const float*)d_in[10];
    float* out = (float*)d_out;

    cudaFuncSetAttribute(edge_kernel,
                         cudaFuncAttributeMaxDynamicSharedMemorySize, GEMM_DYN_SMEM);
    cudaFuncSetAttribute(qkv_kernel,
                         cudaFuncAttributeMaxDynamicSharedMemorySize, GEMM_DYN_SMEM);

    prep_kernel<<<(4 * DIM * DIM + 255) / 256, 256>>>(We, Wq, Wk, Wv);

    zero_kernel<<<(N_NODES * DIM + 255) / 256, 256>>>(out);

    dim3 gqkv((N_NODES + EBM - 1) / EBM, 1, 3);
    qkv_kernel<<<gqkv, 256, GEMM_DYN_SMEM>>>(x, bq, bk, bv);

    edge_kernel<<<N_EDGES / EBM, 256, GEMM_DYN_SMEM>>>(ea, eidx, be, out);

    finalize_kernel<<<(N_NODES * 32 + 255) / 256, 256>>>(out);
}